// round 1
// baseline (speedup 1.0000x reference)
#include <cuda_runtime.h>
#include <math.h>

#define N_NODES 100000
#define N_EDGES 1600000
#define EF 16
#define EH 32
#define NF 128
#define IN1 160            // EH + NF
#define TM 32              // nodes per tile in node kernel
#define NTILES ((N_NODES + TM - 1) / TM)

// Scratch (device globals: allocation-free)
__device__ float g_denom[N_NODES];
__device__ float g_c[(size_t)N_NODES * EH];
__device__ unsigned int g_tilectr;

// ---------------------------------------------------------------------------
// init: zero accumulators + reset work-stealing counter
// ---------------------------------------------------------------------------
__global__ void init_kernel() {
    int i = blockIdx.x * blockDim.x + threadIdx.x;
    if (i == 0) g_tilectr = 0u;
    if (i < N_NODES) g_denom[i] = 0.0f;
    if (i < N_NODES * EH) g_c[i] = 0.0f;
}

// ---------------------------------------------------------------------------
// edge kernel: per edge e with destination d:
//   ex = exp(logit[e])                      (max-shift skipped: pure renorm)
//   et = edge_feats[e] @ W_et + b_et        (16 -> 32)
//   denom[d]   += ex          (scalar atomic)
//   c_unnorm[d] += ex * et    (red.global.add.v4.f32 x 8)
// ---------------------------------------------------------------------------
__global__ __launch_bounds__(256) void edge_kernel(
    const float* __restrict__ logits,
    const float* __restrict__ feats,
    const int*   __restrict__ dst,
    const float* __restrict__ W_et,
    const float* __restrict__ b_et)
{
    __shared__ float sW[EF * EH];
    __shared__ float sb[EH];
    for (int i = threadIdx.x; i < EF * EH; i += blockDim.x) sW[i] = W_et[i];
    if (threadIdx.x < EH) sb[threadIdx.x] = b_et[threadIdx.x];
    __syncthreads();

    int e = blockIdx.x * blockDim.x + threadIdx.x;
    if (e >= N_EDGES) return;

    float ex = expf(logits[e]);
    int d = dst[e];

    const float4* f4 = reinterpret_cast<const float4*>(feats + (size_t)e * EF);
    float4 q0 = f4[0], q1 = f4[1], q2 = f4[2], q3 = f4[3];
    float f[EF] = {q0.x, q0.y, q0.z, q0.w,
                   q1.x, q1.y, q1.z, q1.w,
                   q2.x, q2.y, q2.z, q2.w,
                   q3.x, q3.y, q3.z, q3.w};

    float et[EH];
    const float4* sb4 = reinterpret_cast<const float4*>(sb);
#pragma unroll
    for (int j4 = 0; j4 < EH / 4; j4++) {
        float4 b = sb4[j4];
        et[4 * j4 + 0] = b.x; et[4 * j4 + 1] = b.y;
        et[4 * j4 + 2] = b.z; et[4 * j4 + 3] = b.w;
    }

    const float4* sW4 = reinterpret_cast<const float4*>(sW);
#pragma unroll
    for (int k = 0; k < EF; k++) {
        float fv = f[k];
#pragma unroll
        for (int j4 = 0; j4 < EH / 4; j4++) {
            float4 w = sW4[k * (EH / 4) + j4];
            et[4 * j4 + 0] = fmaf(fv, w.x, et[4 * j4 + 0]);
            et[4 * j4 + 1] = fmaf(fv, w.y, et[4 * j4 + 1]);
            et[4 * j4 + 2] = fmaf(fv, w.z, et[4 * j4 + 2]);
            et[4 * j4 + 3] = fmaf(fv, w.w, et[4 * j4 + 3]);
        }
    }

    atomicAdd(&g_denom[d], ex);

    float* cp = &g_c[(size_t)d * EH];
#pragma unroll
    for (int j = 0; j < EH; j += 4) {
        float x0 = ex * et[j + 0];
        float x1 = ex * et[j + 1];
        float x2 = ex * et[j + 2];
        float x3 = ex * et[j + 3];
        asm volatile("red.global.add.v4.f32 [%0], {%1, %2, %3, %4};"
                     :: "l"(cp + j), "f"(x0), "f"(x1), "f"(x2), "f"(x3)
                     : "memory");
    }
}

// ---------------------------------------------------------------------------
// node kernel: per node n:
//   ctx = elu(c_unnorm[n] / max-ish(denom[n]))     (denom==0 -> 1)
//   h   = relu([ctx | node_feats[n]] @ W1 + b1)
//   out = relu(h @ W2 + b2)
// Both weight matrices live in shared (147 KB); 32-node tiles; work-stealing.
// ---------------------------------------------------------------------------
#define SMEM_FLOATS (IN1 * NF + NF * NF + TM * IN1 + TM * NF + 2 * NF)
#define SMEM_BYTES  (SMEM_FLOATS * 4)

__global__ __launch_bounds__(256, 1) void node_kernel(
    const float* __restrict__ node_feats,
    const float* __restrict__ W1,
    const float* __restrict__ b1,
    const float* __restrict__ W2,
    const float* __restrict__ b2,
    float* __restrict__ out)
{
    __shared__ unsigned s_tile;
    extern __shared__ float smem[];
    float* sW1 = smem;                    // 160*128
    float* sW2 = sW1 + IN1 * NF;          // 128*128
    float* sA  = sW2 + NF * NF;           // 32*160
    float* sH  = sA + TM * IN1;           // 32*128
    float* sb1 = sH + TM * NF;            // 128
    float* sb2 = sb1 + NF;                // 128

    // Grab first tile BEFORE loading weights so surplus CTAs exit instantly.
    if (threadIdx.x == 0) s_tile = atomicAdd(&g_tilectr, 1u);
    __syncthreads();
    unsigned tile = s_tile;
    if (tile >= NTILES) return;

    for (int i = threadIdx.x; i < IN1 * NF; i += 256) sW1[i] = W1[i];
    for (int i = threadIdx.x; i < NF * NF; i += 256)  sW2[i] = W2[i];
    if (threadIdx.x < NF) {
        sb1[threadIdx.x] = b1[threadIdx.x];
        sb2[threadIdx.x] = b2[threadIdx.x];
    }
    __syncthreads();

    const int j = threadIdx.x & 127;      // output column
    const int g = threadIdx.x >> 7;       // node half (0/1)

    while (tile < NTILES) {
        int base = (int)tile * TM;

        // ---- stage inputs: ctx (with normalize + elu) and node feats ----
        for (int i = threadIdx.x; i < TM * EH; i += 256) {
            int n = i / EH, jj = i % EH;
            int node = base + n;
            float v = 0.0f;
            if (node < N_NODES) {
                float den = g_denom[node];
                if (den == 0.0f) den = 1.0f;
                float cv = g_c[(size_t)node * EH + jj] / den;
                v = (cv > 0.0f) ? cv : expm1f(cv);
            }
            sA[n * IN1 + jj] = v;
        }
        for (int i = threadIdx.x; i < TM * NF; i += 256) {
            int n = i / NF, ff = i % NF;
            int node = base + n;
            sA[n * IN1 + EH + ff] =
                (node < N_NODES) ? node_feats[(size_t)node * NF + ff] : 0.0f;
        }
        __syncthreads();

        // ---- GEMM1: [32 x 160] @ [160 x 128] ----
        float acc[16];
#pragma unroll
        for (int m = 0; m < 16; m++) acc[m] = sb1[j];

        for (int k = 0; k < IN1; k += 4) {
            float4 av[16];
#pragma unroll
            for (int m = 0; m < 16; m++)
                av[m] = *reinterpret_cast<const float4*>(&sA[(g * 16 + m) * IN1 + k]);
            float w0 = sW1[(k + 0) * NF + j];
            float w1 = sW1[(k + 1) * NF + j];
            float w2 = sW1[(k + 2) * NF + j];
            float w3 = sW1[(k + 3) * NF + j];
#pragma unroll
            for (int m = 0; m < 16; m++) acc[m] = fmaf(av[m].x, w0, acc[m]);
#pragma unroll
            for (int m = 0; m < 16; m++) acc[m] = fmaf(av[m].y, w1, acc[m]);
#pragma unroll
            for (int m = 0; m < 16; m++) acc[m] = fmaf(av[m].z, w2, acc[m]);
#pragma unroll
            for (int m = 0; m < 16; m++) acc[m] = fmaf(av[m].w, w3, acc[m]);
        }
#pragma unroll
        for (int m = 0; m < 16; m++)
            sH[(g * 16 + m) * NF + j] = fmaxf(acc[m], 0.0f);
        __syncthreads();

        // ---- GEMM2: [32 x 128] @ [128 x 128] ----
        float acc2[16];
#pragma unroll
        for (int m = 0; m < 16; m++) acc2[m] = sb2[j];

        for (int k = 0; k < NF; k += 4) {
            float4 hv[16];
#pragma unroll
            for (int m = 0; m < 16; m++)
                hv[m] = *reinterpret_cast<const float4*>(&sH[(g * 16 + m) * NF + k]);
            float w0 = sW2[(k + 0) * NF + j];
            float w1 = sW2[(k + 1) * NF + j];
            float w2 = sW2[(k + 2) * NF + j];
            float w3 = sW2[(k + 3) * NF + j];
#pragma unroll
            for (int m = 0; m < 16; m++) acc2[m] = fmaf(hv[m].x, w0, acc2[m]);
#pragma unroll
            for (int m = 0; m < 16; m++) acc2[m] = fmaf(hv[m].y, w1, acc2[m]);
#pragma unroll
            for (int m = 0; m < 16; m++) acc2[m] = fmaf(hv[m].z, w2, acc2[m]);
#pragma unroll
            for (int m = 0; m < 16; m++) acc2[m] = fmaf(hv[m].w, w3, acc2[m]);
        }

#pragma unroll
        for (int m = 0; m < 16; m++) {
            int node = base + g * 16 + m;
            if (node < N_NODES)
                out[(size_t)node * NF + j] = fmaxf(acc2[m], 0.0f);
        }
        __syncthreads();

        // ---- steal next tile ----
        if (threadIdx.x == 0) s_tile = atomicAdd(&g_tilectr, 1u);
        __syncthreads();
        tile = s_tile;
    }
}

// ---------------------------------------------------------------------------
extern "C" void kernel_launch(void* const* d_in, const int* in_sizes, int n_in,
                              void* d_out, int out_size)
{
    const float* edge_logits = (const float*)d_in[0];
    const float* edge_feats  = (const float*)d_in[1];
    const float* node_feats  = (const float*)d_in[2];
    const int*   dst         = (const int*)d_in[3];
    const float* W_et        = (const float*)d_in[4];
    const float* b_et        = (const float*)d_in[5];
    const float* W1          = (const float*)d_in[6];
    const float* b1          = (const float*)d_in[7];
    const float* W2          = (const float*)d_in[8];
    const float* b2          = (const float*)d_in[9];
    float* out = (float*)d_out;

    cudaFuncSetAttribute(node_kernel,
                         cudaFuncAttributeMaxDynamicSharedMemorySize, SMEM_BYTES);

    int init_total = N_NODES * EH;   // covers g_c and g_denom and counter
    init_kernel<<<(init_total + 255) / 256, 256>>>();
    edge_kernel<<<(N_EDGES + 255) / 256, 256>>>(edge_logits, edge_feats, dst,
                                                W_et, b_et);
    node_kernel<<<152, 256, SMEM_BYTES>>>(node_feats, W1, b1, W2, b2, out);
}

// round 2
// speedup vs baseline: 1.1125x; 1.1125x over previous
#include <cuda_runtime.h>
#include <math.h>

#define N_NODES 100000
#define N_EDGES 1600000
#define EF 16
#define EH 32
#define NF 128
#define IN1 160            // EH + NF
#define TM 32              // nodes per tile (100000/32 = 3125 exact)
#define NTILES (N_NODES / TM)
#define AT_STRIDE 36       // padded node-stride for transposed tiles

// packed f32x2 helpers (sm_100+)
#define PACK2(d, lo, hi)  asm("mov.b64 %0, {%1, %2};" : "=l"(d) : "f"(lo), "f"(hi))
#define UNPACK2(lo, hi, s) asm("mov.b64 {%0, %1}, %2;" : "=f"(lo), "=f"(hi) : "l"(s))
#define FMA2(d, a, b, c)  asm("fma.rn.f32x2 %0, %1, %2, %3;" : "=l"(d) : "l"(a), "l"(b), "l"(c))
#define MUL2(d, a, b)     asm("mul.rn.f32x2 %0, %1, %2;" : "=l"(d) : "l"(a), "l"(b))

// Scratch (device globals: allocation-free)
__device__ __align__(16) float g_denom[N_NODES];
__device__ __align__(16) float g_c[(size_t)N_NODES * EH];
__device__ unsigned int g_tilectr;

// ---------------------------------------------------------------------------
// init: zero accumulators (vectorized) + reset work-stealing counter
// ---------------------------------------------------------------------------
#define NC4 (N_NODES * EH / 4)     // 800000
#define ND4 (N_NODES / 4)          // 25000
#define NINIT (NC4 + ND4)          // 825000
__global__ void init_kernel() {
    int i = blockIdx.x * blockDim.x + threadIdx.x;
    if (i == 0) g_tilectr = 0u;
    float4 z = make_float4(0.f, 0.f, 0.f, 0.f);
    if (i < NC4) {
        reinterpret_cast<float4*>(g_c)[i] = z;
    } else if (i < NINIT) {
        reinterpret_cast<float4*>(g_denom)[i - NC4] = z;
    }
}

// ---------------------------------------------------------------------------
// edge kernel: ex = exp(logit); et = feats @ W_et + b_et (packed FFMA2);
// denom[d] += ex; c[d] += ex*et (red.v4)
// ---------------------------------------------------------------------------
__global__ __launch_bounds__(256) void edge_kernel(
    const float* __restrict__ logits,
    const float* __restrict__ feats,
    const int*   __restrict__ dst,
    const float* __restrict__ W_et,
    const float* __restrict__ b_et)
{
    __shared__ __align__(16) float sW[EF * EH];
    __shared__ __align__(16) float sb[EH];
    for (int i = threadIdx.x; i < EF * EH; i += blockDim.x) sW[i] = W_et[i];
    if (threadIdx.x < EH) sb[threadIdx.x] = b_et[threadIdx.x];
    __syncthreads();

    int e = blockIdx.x * blockDim.x + threadIdx.x;   // exact: 6250*256

    float ex = __expf(logits[e]);
    int d = dst[e];

    const float4* f4 = reinterpret_cast<const float4*>(feats + (size_t)e * EF);
    float4 q0 = f4[0], q1 = f4[1], q2 = f4[2], q3 = f4[3];
    float f[EF] = {q0.x, q0.y, q0.z, q0.w,
                   q1.x, q1.y, q1.z, q1.w,
                   q2.x, q2.y, q2.z, q2.w,
                   q3.x, q3.y, q3.z, q3.w};

    unsigned long long acc[EH / 2];   // 16 packed pairs
    {
        const ulonglong2* b2 = reinterpret_cast<const ulonglong2*>(sb);
#pragma unroll
        for (int q = 0; q < EH / 4; q++) {        // 8 x ulonglong2 = 16 pairs
            ulonglong2 v = b2[q];
            acc[2 * q + 0] = v.x;
            acc[2 * q + 1] = v.y;
        }
    }

#pragma unroll
    for (int k = 0; k < EF; k++) {
        unsigned long long fv2;
        PACK2(fv2, f[k], f[k]);
        const ulonglong2* w2 = reinterpret_cast<const ulonglong2*>(sW + k * EH);
#pragma unroll
        for (int q = 0; q < EH / 4; q++) {
            ulonglong2 w = w2[q];
            FMA2(acc[2 * q + 0], fv2, w.x, acc[2 * q + 0]);
            FMA2(acc[2 * q + 1], fv2, w.y, acc[2 * q + 1]);
        }
    }

    atomicAdd(&g_denom[d], ex);

    unsigned long long ex2;
    PACK2(ex2, ex, ex);
    float* cp = &g_c[(size_t)d * EH];
#pragma unroll
    for (int j = 0; j < EH / 8; j++) {            // 4 x red.v4 (8 floats each)… 8 total
        // two red.v4 per iteration: 8 pairs -> handled as j over 4 groups of 4 pairs
        unsigned long long p0, p1, p2, p3;
        MUL2(p0, acc[4 * j + 0], ex2);
        MUL2(p1, acc[4 * j + 1], ex2);
        MUL2(p2, acc[4 * j + 2], ex2);
        MUL2(p3, acc[4 * j + 3], ex2);
        float x0, x1, x2, x3, x4, x5, x6, x7;
        UNPACK2(x0, x1, p0); UNPACK2(x2, x3, p1);
        UNPACK2(x4, x5, p2); UNPACK2(x6, x7, p3);
        asm volatile("red.global.add.v4.f32 [%0], {%1, %2, %3, %4};"
                     :: "l"(cp + 8 * j), "f"(x0), "f"(x1), "f"(x2), "f"(x3)
                     : "memory");
        asm volatile("red.global.add.v4.f32 [%0], {%1, %2, %3, %4};"
                     :: "l"(cp + 8 * j + 4), "f"(x4), "f"(x5), "f"(x6), "f"(x7)
                     : "memory");
    }
}

// ---------------------------------------------------------------------------
// node kernel (packed FFMA2 over node pairs, transposed A/H tiles)
// ---------------------------------------------------------------------------
#define SM_W1 0
#define SM_W2 (SM_W1 + IN1 * NF)          // 20480
#define SM_AT (SM_W2 + NF * NF)           // 36864
#define SM_HT (SM_AT + IN1 * AT_STRIDE)   // +5760
#define SM_B1 (SM_HT + NF * AT_STRIDE)    // +4608
#define SM_B2 (SM_B1 + NF)
#define SMEM_FLOATS (SM_B2 + NF)
#define SMEM_BYTES  (SMEM_FLOATS * 4)

__global__ __launch_bounds__(256, 1) void node_kernel(
    const float* __restrict__ node_feats,
    const float* __restrict__ W1,
    const float* __restrict__ b1,
    const float* __restrict__ W2,
    const float* __restrict__ b2,
    float* __restrict__ out)
{
    __shared__ unsigned s_tile;
    extern __shared__ __align__(16) float smem[];
    float* sW1 = smem + SM_W1;
    float* sW2 = smem + SM_W2;
    float* sAt = smem + SM_AT;   // [IN1][AT_STRIDE] transposed input tile
    float* sHt = smem + SM_HT;   // [NF][AT_STRIDE]  transposed hidden tile
    float* sb1 = smem + SM_B1;
    float* sb2 = smem + SM_B2;

    if (threadIdx.x == 0) s_tile = atomicAdd(&g_tilectr, 1u);
    __syncthreads();
    unsigned tile = s_tile;
    if (tile >= NTILES) return;

    for (int i = threadIdx.x; i < IN1 * NF; i += 256) sW1[i] = W1[i];
    for (int i = threadIdx.x; i < NF * NF; i += 256)  sW2[i] = W2[i];
    if (threadIdx.x < NF) {
        sb1[threadIdx.x] = b1[threadIdx.x];
        sb2[threadIdx.x] = b2[threadIdx.x];
    }
    __syncthreads();

    const int j = threadIdx.x & 127;      // output column
    const int g = threadIdx.x >> 7;       // node half (0/1), 16 nodes each

    while (tile < NTILES) {
        int base = (int)tile * TM;

        // ---- stage ctx (normalize + elu) transposed ----
        for (int i = threadIdx.x; i < TM * EH; i += 256) {
            int n = i >> 5, jj = i & 31;
            int node = base + n;
            float den = g_denom[node];
            if (den == 0.0f) den = 1.0f;
            float cv = g_c[(size_t)node * EH + jj] / den;
            sAt[jj * AT_STRIDE + n] = (cv > 0.0f) ? cv : expm1f(cv);
        }
        // ---- stage node feats transposed (gmem reads stay coalesced) ----
        for (int i = threadIdx.x; i < TM * NF; i += 256) {
            int n = i >> 7, ff = i & 127;
            sAt[(EH + ff) * AT_STRIDE + n] =
                node_feats[(size_t)(base + n) * NF + ff];
        }
        __syncthreads();

        // ---- GEMM1: acc[m] = packed node-pair (2m,2m+1) at column j ----
        unsigned long long acc[8];
        {
            float bv = sb1[j];
            unsigned long long b2v; PACK2(b2v, bv, bv);
#pragma unroll
            for (int m = 0; m < 8; m++) acc[m] = b2v;
        }
        {
            const char* aBase = reinterpret_cast<const char*>(sAt + g * 16);
#pragma unroll 4
            for (int k = 0; k < IN1; k++) {
                float w = sW1[k * NF + j];
                unsigned long long w2v; PACK2(w2v, w, w);
                const ulonglong2* ap =
                    reinterpret_cast<const ulonglong2*>(aBase + k * (AT_STRIDE * 4));
                ulonglong2 a0 = ap[0], a1 = ap[1], a2 = ap[2], a3 = ap[3];
                FMA2(acc[0], a0.x, w2v, acc[0]);
                FMA2(acc[1], a0.y, w2v, acc[1]);
                FMA2(acc[2], a1.x, w2v, acc[2]);
                FMA2(acc[3], a1.y, w2v, acc[3]);
                FMA2(acc[4], a2.x, w2v, acc[4]);
                FMA2(acc[5], a2.y, w2v, acc[5]);
                FMA2(acc[6], a3.x, w2v, acc[6]);
                FMA2(acc[7], a3.y, w2v, acc[7]);
            }
        }
        // relu -> sHt transposed
#pragma unroll
        for (int m = 0; m < 8; m++) {
            float lo, hi; UNPACK2(lo, hi, acc[m]);
            lo = fmaxf(lo, 0.0f); hi = fmaxf(hi, 0.0f);
            *reinterpret_cast<float2*>(&sHt[j * AT_STRIDE + g * 16 + 2 * m]) =
                make_float2(lo, hi);
        }
        __syncthreads();

        // ---- GEMM2 ----
        unsigned long long acc2[8];
        {
            float bv = sb2[j];
            unsigned long long b2v; PACK2(b2v, bv, bv);
#pragma unroll
            for (int m = 0; m < 8; m++) acc2[m] = b2v;
        }
        {
            const char* hBase = reinterpret_cast<const char*>(sHt + g * 16);
#pragma unroll 4
            for (int k = 0; k < NF; k++) {
                float w = sW2[k * NF + j];
                unsigned long long w2v; PACK2(w2v, w, w);
                const ulonglong2* hp =
                    reinterpret_cast<const ulonglong2*>(hBase + k * (AT_STRIDE * 4));
                ulonglong2 h0 = hp[0], h1 = hp[1], h2 = hp[2], h3 = hp[3];
                FMA2(acc2[0], h0.x, w2v, acc2[0]);
                FMA2(acc2[1], h0.y, w2v, acc2[1]);
                FMA2(acc2[2], h1.x, w2v, acc2[2]);
                FMA2(acc2[3], h1.y, w2v, acc2[3]);
                FMA2(acc2[4], h2.x, w2v, acc2[4]);
                FMA2(acc2[5], h2.y, w2v, acc2[5]);
                FMA2(acc2[6], h3.x, w2v, acc2[6]);
                FMA2(acc2[7], h3.y, w2v, acc2[7]);
            }
        }
#pragma unroll
        for (int m = 0; m < 8; m++) {
            float lo, hi; UNPACK2(lo, hi, acc2[m]);
            int node = base + g * 16 + 2 * m;
            out[(size_t)node * NF + j]       = fmaxf(lo, 0.0f);
            out[(size_t)(node + 1) * NF + j] = fmaxf(hi, 0.0f);
        }
        __syncthreads();

        if (threadIdx.x == 0) s_tile = atomicAdd(&g_tilectr, 1u);
        __syncthreads();
        tile = s_tile;
    }
}

// ---------------------------------------------------------------------------
extern "C" void kernel_launch(void* const* d_in, const int* in_sizes, int n_in,
                              void* d_out, int out_size)
{
    const float* edge_logits = (const float*)d_in[0];
    const float* edge_feats  = (const float*)d_in[1];
    const float* node_feats  = (const float*)d_in[2];
    const int*   dst         = (const int*)d_in[3];
    const float* W_et        = (const float*)d_in[4];
    const float* b_et        = (const float*)d_in[5];
    const float* W1          = (const float*)d_in[6];
    const float* b1          = (const float*)d_in[7];
    const float* W2          = (const float*)d_in[8];
    const float* b2          = (const float*)d_in[9];
    float* out = (float*)d_out;

    cudaFuncSetAttribute(node_kernel,
                         cudaFuncAttributeMaxDynamicSharedMemorySize, SMEM_BYTES);

    init_kernel<<<(NINIT + 255) / 256, 256>>>();
    edge_kernel<<<N_EDGES / 256, 256>>>(edge_logits, edge_feats, dst,
                                        W_et, b_et);
    node_kernel<<<152, 256, SMEM_BYTES>>>(node_feats, W1, b1, W2, b2, out);
}

// round 4
// speedup vs baseline: 1.3914x; 1.2506x over previous
#include <cuda_runtime.h>
#include <math.h>
#include <stdint.h>

#define N_NODES 100000
#define N_EDGES 1600000
#define EF 16
#define EH 32
#define NF 128
#define K1 160             // EH + NF
#define TM 64              // nodes per tile
#define NT_TILES ((N_NODES + TM - 1) / TM)   // 1563
#define AT_STRIDE 68       // padded node-stride (16B-aligned rows, low conflicts)

// packed f32x2 helpers
#define PACK2(d, lo, hi)  asm("mov.b64 %0, {%1, %2};" : "=l"(d) : "f"(lo), "f"(hi))
#define UNPACK2(lo, hi, s) asm("mov.b64 {%0, %1}, %2;" : "=f"(lo), "=f"(hi) : "l"(s))
#define FMA2(d, a, b, c)  asm("fma.rn.f32x2 %0, %1, %2, %3;" : "=l"(d) : "l"(a), "l"(b), "l"(c))

// ---------------- device scratch (allocation-free) ----------------
__device__ __align__(16) float g_denom[N_NODES];
__device__ __align__(16) float g_s[(size_t)N_NODES * EF];   // sum of ex * edge_feats
__device__ unsigned int g_ctr;

// ---------------------------------------------------------------------------
// init: zero accumulators + counter
// ---------------------------------------------------------------------------
#define NS4 (N_NODES * EF / 4)     // 400000
#define ND4 (N_NODES / 4)          // 25000
#define NINIT (NS4 + ND4)          // 425000
__global__ void init_kernel() {
    int i = blockIdx.x * blockDim.x + threadIdx.x;
    if (i == 0) g_ctr = 0u;
    float4 z = make_float4(0.f, 0.f, 0.f, 0.f);
    if (i < NS4) {
        reinterpret_cast<float4*>(g_s)[i] = z;
    } else if (i < NINIT) {
        reinterpret_cast<float4*>(g_denom)[i - NS4] = z;
    }
}

// ---------------------------------------------------------------------------
// edge kernel: ex = exp(logit); denom[d] += ex; s[d] += ex * feats[e]
// (edge MLP transform is deferred to the node kernel: sum(alpha)=1 identity)
// ---------------------------------------------------------------------------
__global__ __launch_bounds__(256) void edge_kernel(
    const float* __restrict__ logits,
    const float* __restrict__ feats,
    const int*   __restrict__ dst)
{
    int e = blockIdx.x * blockDim.x + threadIdx.x;   // exact: 6250*256

    float ex = __expf(logits[e]);
    int d = dst[e];

    const float4* f4 = reinterpret_cast<const float4*>(feats + (size_t)e * EF);
    float4 q0 = f4[0], q1 = f4[1], q2 = f4[2], q3 = f4[3];

    atomicAdd(&g_denom[d], ex);

    float* sp = &g_s[(size_t)d * EF];
    asm volatile("red.global.add.v4.f32 [%0], {%1, %2, %3, %4};"
                 :: "l"(sp + 0), "f"(ex * q0.x), "f"(ex * q0.y),
                    "f"(ex * q0.z), "f"(ex * q0.w) : "memory");
    asm volatile("red.global.add.v4.f32 [%0], {%1, %2, %3, %4};"
                 :: "l"(sp + 4), "f"(ex * q1.x), "f"(ex * q1.y),
                    "f"(ex * q1.z), "f"(ex * q1.w) : "memory");
    asm volatile("red.global.add.v4.f32 [%0], {%1, %2, %3, %4};"
                 :: "l"(sp + 8), "f"(ex * q2.x), "f"(ex * q2.y),
                    "f"(ex * q2.z), "f"(ex * q2.w) : "memory");
    asm volatile("red.global.add.v4.f32 [%0], {%1, %2, %3, %4};"
                 :: "l"(sp + 12), "f"(ex * q3.x), "f"(ex * q3.y),
                    "f"(ex * q3.z), "f"(ex * q3.w) : "memory");
}

// ---------------------------------------------------------------------------
// node kernel: ctx = elu((s/denom) @ W_et + b_et)
//              h   = relu([ctx | feats] @ W1 + b1)
//              out = relu(h @ W2 + b2)
// W1+W2 resident in smem; TM=64 tiles; 512 threads; packed-FMA2 GEMMs.
// ---------------------------------------------------------------------------
#define SM_W1  0
#define SM_W2  (SM_W1 + K1 * NF)            // +20480
#define SM_AT  (SM_W2 + NF * NF)            // +16384
#define SM_HT  (SM_AT + K1 * AT_STRIDE)     // +10880
#define SM_WET (SM_HT + NF * AT_STRIDE)     // +8704
#define SM_BET (SM_WET + EF * EH)           // +512
#define SM_B1  (SM_BET + EH)                // +32
#define SM_B2  (SM_B1 + NF)
#define SMEM_FLOATS (SM_B2 + NF)
#define SMEM_BYTES  (SMEM_FLOATS * 4)       // 228,992 B

__global__ __launch_bounds__(512, 1) void node_kernel(
    const float* __restrict__ node_feats,
    const float* __restrict__ W_et,
    const float* __restrict__ b_et,
    const float* __restrict__ W1,
    const float* __restrict__ b1,
    const float* __restrict__ W2,
    const float* __restrict__ b2,
    float* __restrict__ out)
{
    __shared__ unsigned s_tile;
    extern __shared__ __align__(16) float smem[];
    float* sW1  = smem + SM_W1;
    float* sW2  = smem + SM_W2;
    float* sAt  = smem + SM_AT;    // [K1][AT_STRIDE] transposed input tile
    float* sHt  = smem + SM_HT;    // [NF][AT_STRIDE] transposed hidden tile
    float* sWet = smem + SM_WET;   // [EF][EH]
    float* sbet = smem + SM_BET;
    float* sb1  = smem + SM_B1;
    float* sb2  = smem + SM_B2;

    const int tid = threadIdx.x;

    if (tid == 0) s_tile = atomicAdd(&g_ctr, 1u);
    __syncthreads();
    unsigned tile = s_tile;
    if (tile >= NT_TILES) return;

    for (int i = tid; i < K1 * NF; i += 512) sW1[i] = W1[i];
    for (int i = tid; i < NF * NF; i += 512) sW2[i] = W2[i];
    if (tid < EF * EH) sWet[tid] = W_et[tid];
    if (tid < EH) sbet[tid] = b_et[tid];
    if (tid < NF) { sb1[tid] = b1[tid]; sb2[tid] = b2[tid]; }
    __syncthreads();

    const int j = tid & 127;       // output column
    const int g = tid >> 7;        // node group (0..3), 16 nodes each

    while (tile < NT_TILES) {
        int base = (int)tile * TM;

        // ---- stage ctx: t = s/denom; et = t @ W_et + b_et; elu; transpose ----
        {
            int n = tid >> 3;            // 0..63
            int p = tid & 7;             // j-subgroup: columns p*4..p*4+3
            int node = base + n;
            float t[EF];
            if (node < N_NODES) {
                float den = g_denom[node];
                if (den == 0.0f) den = 1.0f;
                float inv = 1.0f / den;
                const float4* sp = reinterpret_cast<const float4*>(g_s + (size_t)node * EF);
                float4 a = sp[0], b = sp[1], c = sp[2], d = sp[3];
                t[0] = a.x * inv;  t[1] = a.y * inv;  t[2] = a.z * inv;  t[3] = a.w * inv;
                t[4] = b.x * inv;  t[5] = b.y * inv;  t[6] = b.z * inv;  t[7] = b.w * inv;
                t[8] = c.x * inv;  t[9] = c.y * inv;  t[10] = c.z * inv; t[11] = c.w * inv;
                t[12] = d.x * inv; t[13] = d.y * inv; t[14] = d.z * inv; t[15] = d.w * inv;
            } else {
#pragma unroll
                for (int k = 0; k < EF; k++) t[k] = 0.0f;
            }
#pragma unroll
            for (int jj = 0; jj < 4; jj++) {
                int jc = p * 4 + jj;
                float acc = sbet[jc];
#pragma unroll
                for (int k = 0; k < EF; k++)
                    acc = fmaf(t[k], sWet[k * EH + jc], acc);
                float v = (acc > 0.0f) ? acc : expm1f(acc);
                if (node >= N_NODES) v = 0.0f;
                sAt[jc * AT_STRIDE + n] = v;
            }
        }
        // ---- stage node feats transposed (coalesced gmem reads) ----
        for (int i = tid; i < TM * NF; i += 512) {
            int n = i >> 7, f = i & 127;
            int node = base + n;
            sAt[(EH + f) * AT_STRIDE + n] =
                (node < N_NODES) ? node_feats[(size_t)node * NF + f] : 0.0f;
        }
        __syncthreads();

        // ---- GEMM1: acc[m] = node-pair (2m,2m+1) of group g at column j ----
        unsigned long long acc[8];
        {
            float bv = sb1[j];
            unsigned long long b2v; PACK2(b2v, bv, bv);
#pragma unroll
            for (int m = 0; m < 8; m++) acc[m] = b2v;
        }
#pragma unroll 4
        for (int k = 0; k < K1; k++) {
            float w = sW1[k * NF + j];
            unsigned long long w2v; PACK2(w2v, w, w);
            const ulonglong2* ap =
                reinterpret_cast<const ulonglong2*>(sAt + k * AT_STRIDE + g * 16);
            ulonglong2 a0 = ap[0], a1 = ap[1], a2 = ap[2], a3 = ap[3];
            FMA2(acc[0], a0.x, w2v, acc[0]);
            FMA2(acc[1], a0.y, w2v, acc[1]);
            FMA2(acc[2], a1.x, w2v, acc[2]);
            FMA2(acc[3], a1.y, w2v, acc[3]);
            FMA2(acc[4], a2.x, w2v, acc[4]);
            FMA2(acc[5], a2.y, w2v, acc[5]);
            FMA2(acc[6], a3.x, w2v, acc[6]);
            FMA2(acc[7], a3.y, w2v, acc[7]);
        }
#pragma unroll
        for (int m = 0; m < 8; m++) {
            float lo, hi; UNPACK2(lo, hi, acc[m]);
            lo = fmaxf(lo, 0.0f); hi = fmaxf(hi, 0.0f);
            *reinterpret_cast<float2*>(&sHt[j * AT_STRIDE + g * 16 + 2 * m]) =
                make_float2(lo, hi);
        }
        __syncthreads();

        // ---- GEMM2 ----
        unsigned long long acc2[8];
        {
            float bv = sb2[j];
            unsigned long long b2v; PACK2(b2v, bv, bv);
#pragma unroll
            for (int m = 0; m < 8; m++) acc2[m] = b2v;
        }
#pragma unroll 4
        for (int k = 0; k < NF; k++) {
            float w = sW2[k * NF + j];
            unsigned long long w2v; PACK2(w2v, w, w);
            const ulonglong2* hp =
                reinterpret_cast<const ulonglong2*>(sHt + k * AT_STRIDE + g * 16);
            ulonglong2 h0 = hp[0], h1 = hp[1], h2 = hp[2], h3 = hp[3];
            FMA2(acc2[0], h0.x, w2v, acc2[0]);
            FMA2(acc2[1], h0.y, w2v, acc2[1]);
            FMA2(acc2[2], h1.x, w2v, acc2[2]);
            FMA2(acc2[3], h1.y, w2v, acc2[3]);
            FMA2(acc2[4], h2.x, w2v, acc2[4]);
            FMA2(acc2[5], h2.y, w2v, acc2[5]);
            FMA2(acc2[6], h3.x, w2v, acc2[6]);
            FMA2(acc2[7], h3.y, w2v, acc2[7]);
        }
#pragma unroll
        for (int m = 0; m < 8; m++) {
            float lo, hi; UNPACK2(lo, hi, acc2[m]);
            int node = base + g * 16 + 2 * m;
            if (node < N_NODES)
                out[(size_t)node * NF + j] = fmaxf(lo, 0.0f);
            if (node + 1 < N_NODES)
                out[(size_t)(node + 1) * NF + j] = fmaxf(hi, 0.0f);
        }
        __syncthreads();

        if (tid == 0) s_tile = atomicAdd(&g_ctr, 1u);
        __syncthreads();
        tile = s_tile;
    }
}

// ---------------------------------------------------------------------------
extern "C" void kernel_launch(void* const* d_in, const int* in_sizes, int n_in,
                              void* d_out, int out_size)
{
    const float* edge_logits = (const float*)d_in[0];
    const float* edge_feats  = (const float*)d_in[1];
    const float* node_feats  = (const float*)d_in[2];
    const int*   dst         = (const int*)d_in[3];
    const float* W_et        = (const float*)d_in[4];
    const float* b_et        = (const float*)d_in[5];
    const float* W1          = (const float*)d_in[6];
    const float* b1          = (const float*)d_in[7];
    const float* W2          = (const float*)d_in[8];
    const float* b2          = (const float*)d_in[9];
    float* out = (float*)d_out;

    static int configured = 0;
    if (!configured) {
        cudaFuncSetAttribute(node_kernel,
                             cudaFuncAttributeMaxDynamicSharedMemorySize, SMEM_BYTES);
        configured = 1;
    }

    init_kernel<<<(NINIT + 255) / 256, 256>>>();
    edge_kernel<<<N_EDGES / 256, 256>>>(edge_logits, edge_feats, dst);
    node_kernel<<<152, 512, SMEM_BYTES>>>(node_feats, W_et, b_et,
                                          W1, b1, W2, b2, out);
}

// round 5
// speedup vs baseline: 2.0548x; 1.4768x over previous
#include <cuda_runtime.h>
#include <cuda_bf16.h>
#include <math.h>
#include <stdint.h>

#define N_NODES 100000
#define N_EDGES 1600000
#define EF 16
#define EH 32
#define NF 128
#define K1 160             // EH + NF
#define TM 64              // nodes per tile
#define NT_TILES ((N_NODES + TM - 1) / TM)   // 1563
#define SA1 162            // bf16 stride of A / W1t rows (k dimension padded)
#define SH  130            // bf16 stride of H / W2t rows

// ---------------- device scratch (allocation-free) ----------------
__device__ __align__(16) float g_denom[N_NODES];
__device__ __align__(16) float g_s[(size_t)N_NODES * EF];   // sum of ex * edge_feats
__device__ unsigned int g_ctr;

// ---------------------------------------------------------------------------
// init
// ---------------------------------------------------------------------------
#define NS4 (N_NODES * EF / 4)
#define ND4 (N_NODES / 4)
#define NINIT (NS4 + ND4)
__global__ void init_kernel() {
    int i = blockIdx.x * blockDim.x + threadIdx.x;
    if (i == 0) g_ctr = 0u;
    float4 z = make_float4(0.f, 0.f, 0.f, 0.f);
    if (i < NS4) {
        reinterpret_cast<float4*>(g_s)[i] = z;
    } else if (i < NINIT) {
        reinterpret_cast<float4*>(g_denom)[i - NS4] = z;
    }
}

// ---------------------------------------------------------------------------
// edge kernel: ex = exp(logit); denom[d] += ex; s[d] += ex * feats[e]
// ---------------------------------------------------------------------------
__global__ __launch_bounds__(256) void edge_kernel(
    const float* __restrict__ logits,
    const float* __restrict__ feats,
    const int*   __restrict__ dst)
{
    int e = blockIdx.x * blockDim.x + threadIdx.x;

    float ex = __expf(logits[e]);
    int d = dst[e];

    const float4* f4 = reinterpret_cast<const float4*>(feats + (size_t)e * EF);
    float4 q0 = f4[0], q1 = f4[1], q2 = f4[2], q3 = f4[3];

    atomicAdd(&g_denom[d], ex);

    float* sp = &g_s[(size_t)d * EF];
    asm volatile("red.global.add.v4.f32 [%0], {%1, %2, %3, %4};"
                 :: "l"(sp + 0), "f"(ex * q0.x), "f"(ex * q0.y),
                    "f"(ex * q0.z), "f"(ex * q0.w) : "memory");
    asm volatile("red.global.add.v4.f32 [%0], {%1, %2, %3, %4};"
                 :: "l"(sp + 4), "f"(ex * q1.x), "f"(ex * q1.y),
                    "f"(ex * q1.z), "f"(ex * q1.w) : "memory");
    asm volatile("red.global.add.v4.f32 [%0], {%1, %2, %3, %4};"
                 :: "l"(sp + 8), "f"(ex * q2.x), "f"(ex * q2.y),
                    "f"(ex * q2.z), "f"(ex * q2.w) : "memory");
    asm volatile("red.global.add.v4.f32 [%0], {%1, %2, %3, %4};"
                 :: "l"(sp + 12), "f"(ex * q3.x), "f"(ex * q3.y),
                    "f"(ex * q3.z), "f"(ex * q3.w) : "memory");
}

// ---------------------------------------------------------------------------
// node kernel: split-bf16 tensor-core MLP via legacy mma.sync (sm_80+ path)
// ---------------------------------------------------------------------------
// smem layout, bf16-element offsets
#define O_W1H 0
#define O_W1L (O_W1H + NF * SA1)          // 20736
#define O_W2H (O_W1L + NF * SA1)          // 41472
#define O_W2L (O_W2H + NF * SH)           // 58112
#define O_AH  (O_W2L + NF * SH)           // 74752
#define O_AL  (O_AH + TM * SA1)           // 85120
#define O_HH  (O_AL + TM * SA1)           // 95488
#define O_HL  (O_HH + TM * SH)            // 103808
#define O_END (O_HL + TM * SH)            // 112128 bf16 elems
#define O_FLT (O_END * 2)                  // byte offset of float region
#define N_FLT (NF + NF + EF * EH + EH)     // b1, b2, Wet, bet = 800 floats
#define SMEM_BYTES (O_FLT + N_FLT * 4)     // 227,456 B

#define MMA_BF16(c, a0, a1, a2, a3, b0, b1)                                   \
    asm volatile("mma.sync.aligned.m16n8k16.row.col.f32.bf16.bf16.f32 "       \
                 "{%0,%1,%2,%3}, {%4,%5,%6,%7}, {%8,%9}, {%0,%1,%2,%3};"      \
                 : "+f"((c)[0]), "+f"((c)[1]), "+f"((c)[2]), "+f"((c)[3])     \
                 : "r"(a0), "r"(a1), "r"(a2), "r"(a3), "r"(b0), "r"(b1))

__device__ __forceinline__ uint32_t ld2(const __nv_bfloat16* p) {
    return *reinterpret_cast<const uint32_t*>(p);
}
__device__ __forceinline__ void split2(float v, __nv_bfloat16& h, __nv_bfloat16& l) {
    h = __float2bfloat16(v);
    l = __float2bfloat16(v - __bfloat162float(h));
}
__device__ __forceinline__ uint32_t pack_bf(__nv_bfloat16 a, __nv_bfloat16 b) {
    return (uint32_t)__bfloat16_as_ushort(a)
         | ((uint32_t)__bfloat16_as_ushort(b) << 16);
}

__global__ __launch_bounds__(512, 1) void node_kernel(
    const float* __restrict__ node_feats,
    const float* __restrict__ W_et,
    const float* __restrict__ b_et,
    const float* __restrict__ W1,
    const float* __restrict__ b1,
    const float* __restrict__ W2,
    const float* __restrict__ b2,
    float* __restrict__ out)
{
    __shared__ unsigned s_tile;
    extern __shared__ __align__(16) char smem_raw[];
    __nv_bfloat16* sm   = reinterpret_cast<__nv_bfloat16*>(smem_raw);
    __nv_bfloat16* sW1H = sm + O_W1H;
    __nv_bfloat16* sW1L = sm + O_W1L;
    __nv_bfloat16* sW2H = sm + O_W2H;
    __nv_bfloat16* sW2L = sm + O_W2L;
    __nv_bfloat16* sAH  = sm + O_AH;
    __nv_bfloat16* sAL  = sm + O_AL;
    __nv_bfloat16* sHH  = sm + O_HH;
    __nv_bfloat16* sHL  = sm + O_HL;
    float* sb1  = reinterpret_cast<float*>(smem_raw + O_FLT);
    float* sb2  = sb1 + NF;
    float* sWet = sb2 + NF;
    float* sbet = sWet + EF * EH;

    const int tid  = threadIdx.x;
    const int wid  = tid >> 5;
    const int lane = tid & 31;
    const int gq   = lane >> 2;     // fragment group 0..7
    const int tig  = lane & 3;      // thread-in-group
    const int mi   = wid >> 2;      // m-tile 0..3 (16 nodes each)
    const int ni   = wid & 3;       // n-tile 0..3 (32 cols each)

    if (tid == 0) s_tile = atomicAdd(&g_ctr, 1u);
    __syncthreads();
    unsigned tile = s_tile;
    if (tile >= NT_TILES) return;

    // ---- stage weights (transposed + split) ----
    for (int i = tid; i < K1 * NF; i += 512) {
        int k = i >> 7, n = i & 127;
        __nv_bfloat16 h, l; split2(W1[i], h, l);
        sW1H[n * SA1 + k] = h;
        sW1L[n * SA1 + k] = l;
    }
    for (int i = tid; i < NF * NF; i += 512) {
        int k = i >> 7, n = i & 127;
        __nv_bfloat16 h, l; split2(W2[i], h, l);
        sW2H[n * SH + k] = h;
        sW2L[n * SH + k] = l;
    }
    if (tid < EF * EH) sWet[tid] = W_et[tid];
    if (tid < EH) sbet[tid] = b_et[tid];
    if (tid < NF) { sb1[tid] = b1[tid]; sb2[tid] = b2[tid]; }
    __syncthreads();

    while (tile < NT_TILES) {
        int base = (int)tile * TM;

        // ---- stage ctx: t = s/denom; et = t @ W_et + b_et; elu; split ----
        {
            int n = tid >> 3;            // node within tile 0..63
            int p = tid & 7;             // column subgroup
            int node = base + n;
            float t[EF];
            if (node < N_NODES) {
                float den = g_denom[node];
                if (den == 0.0f) den = 1.0f;
                float inv = 1.0f / den;
                const float4* sp = reinterpret_cast<const float4*>(g_s + (size_t)node * EF);
                float4 a = sp[0], b = sp[1], c = sp[2], d = sp[3];
                t[0] = a.x * inv;  t[1] = a.y * inv;  t[2] = a.z * inv;  t[3] = a.w * inv;
                t[4] = b.x * inv;  t[5] = b.y * inv;  t[6] = b.z * inv;  t[7] = b.w * inv;
                t[8] = c.x * inv;  t[9] = c.y * inv;  t[10] = c.z * inv; t[11] = c.w * inv;
                t[12] = d.x * inv; t[13] = d.y * inv; t[14] = d.z * inv; t[15] = d.w * inv;
            } else {
#pragma unroll
                for (int k = 0; k < EF; k++) t[k] = 0.0f;
            }
#pragma unroll
            for (int jj = 0; jj < 4; jj++) {
                int jc = p * 4 + jj;
                float acc = sbet[jc];
#pragma unroll
                for (int k = 0; k < EF; k++)
                    acc = fmaf(t[k], sWet[k * EH + jc], acc);
                float v = (acc > 0.0f) ? acc : expm1f(acc);
                if (node >= N_NODES) v = 0.0f;
                __nv_bfloat16 h, l; split2(v, h, l);
                sAH[n * SA1 + jc] = h;
                sAL[n * SA1 + jc] = l;
            }
        }
        // ---- stage node feats (split) ----
        for (int i = tid; i < TM * NF; i += 512) {
            int n = i >> 7, f = i & 127;
            int node = base + n;
            float v = (node < N_NODES) ? node_feats[(size_t)node * NF + f] : 0.0f;
            __nv_bfloat16 h, l; split2(v, h, l);
            sAH[n * SA1 + EH + f] = h;
            sAL[n * SA1 + EH + f] = l;
        }
        __syncthreads();

        // ================= GEMM1: [64 x 160] @ [160 x 128] =================
        float acc[4][4];
#pragma unroll
        for (int s = 0; s < 4; s++) {
            int col0 = ni * 32 + s * 8 + tig * 2;
            acc[s][0] = sb1[col0];
            acc[s][1] = sb1[col0 + 1];
            acc[s][2] = acc[s][0];
            acc[s][3] = acc[s][1];
        }
        {
            const __nv_bfloat16* aH = sAH + (mi * 16 + gq) * SA1 + tig * 2;
            const __nv_bfloat16* aL = sAL + (mi * 16 + gq) * SA1 + tig * 2;
            const __nv_bfloat16* bH = sW1H + (ni * 32 + gq) * SA1 + tig * 2;
            const __nv_bfloat16* bL = sW1L + (ni * 32 + gq) * SA1 + tig * 2;
#pragma unroll
            for (int kc = 0; kc < K1 / 16; kc++) {
                int ko = kc * 16;
                uint32_t ah0 = ld2(aH + ko),               ah1 = ld2(aH + ko + 8 * SA1);
                uint32_t ah2 = ld2(aH + ko + 8),           ah3 = ld2(aH + ko + 8 * SA1 + 8);
                uint32_t al0 = ld2(aL + ko),               al1 = ld2(aL + ko + 8 * SA1);
                uint32_t al2 = ld2(aL + ko + 8),           al3 = ld2(aL + ko + 8 * SA1 + 8);
#pragma unroll
                for (int s = 0; s < 4; s++) {
                    const __nv_bfloat16* bhs = bH + s * 8 * SA1 + ko;
                    const __nv_bfloat16* bls = bL + s * 8 * SA1 + ko;
                    uint32_t b0h = ld2(bhs), b1h = ld2(bhs + 8);
                    uint32_t b0l = ld2(bls), b1l = ld2(bls + 8);
                    MMA_BF16(acc[s], ah0, ah1, ah2, ah3, b0h, b1h);
                    MMA_BF16(acc[s], ah0, ah1, ah2, ah3, b0l, b1l);
                    MMA_BF16(acc[s], al0, al1, al2, al3, b0h, b1h);
                }
            }
        }
        // epilogue1: relu, split, store H
        {
            int r0 = mi * 16 + gq, r1 = r0 + 8;
#pragma unroll
            for (int s = 0; s < 4; s++) {
                int col0 = ni * 32 + s * 8 + tig * 2;
                float h0 = fmaxf(acc[s][0], 0.0f), h1 = fmaxf(acc[s][1], 0.0f);
                float h2 = fmaxf(acc[s][2], 0.0f), h3 = fmaxf(acc[s][3], 0.0f);
                __nv_bfloat16 a, b, c, d, e, f, g, h;
                split2(h0, a, b); split2(h1, c, d);
                split2(h2, e, f); split2(h3, g, h);
                *reinterpret_cast<uint32_t*>(sHH + r0 * SH + col0) = pack_bf(a, c);
                *reinterpret_cast<uint32_t*>(sHL + r0 * SH + col0) = pack_bf(b, d);
                *reinterpret_cast<uint32_t*>(sHH + r1 * SH + col0) = pack_bf(e, g);
                *reinterpret_cast<uint32_t*>(sHL + r1 * SH + col0) = pack_bf(f, h);
            }
        }
        __syncthreads();

        // ================= GEMM2: [64 x 128] @ [128 x 128] =================
        float acc2[4][4];
#pragma unroll
        for (int s = 0; s < 4; s++) {
            int col0 = ni * 32 + s * 8 + tig * 2;
            acc2[s][0] = sb2[col0];
            acc2[s][1] = sb2[col0 + 1];
            acc2[s][2] = acc2[s][0];
            acc2[s][3] = acc2[s][1];
        }
        {
            const __nv_bfloat16* aH = sHH + (mi * 16 + gq) * SH + tig * 2;
            const __nv_bfloat16* aL = sHL + (mi * 16 + gq) * SH + tig * 2;
            const __nv_bfloat16* bH = sW2H + (ni * 32 + gq) * SH + tig * 2;
            const __nv_bfloat16* bL = sW2L + (ni * 32 + gq) * SH + tig * 2;
#pragma unroll
            for (int kc = 0; kc < NF / 16; kc++) {
                int ko = kc * 16;
                uint32_t ah0 = ld2(aH + ko),               ah1 = ld2(aH + ko + 8 * SH);
                uint32_t ah2 = ld2(aH + ko + 8),           ah3 = ld2(aH + ko + 8 * SH + 8);
                uint32_t al0 = ld2(aL + ko),               al1 = ld2(aL + ko + 8 * SH);
                uint32_t al2 = ld2(aL + ko + 8),           al3 = ld2(aL + ko + 8 * SH + 8);
#pragma unroll
                for (int s = 0; s < 4; s++) {
                    const __nv_bfloat16* bhs = bH + s * 8 * SH + ko;
                    const __nv_bfloat16* bls = bL + s * 8 * SH + ko;
                    uint32_t b0h = ld2(bhs), b1h = ld2(bhs + 8);
                    uint32_t b0l = ld2(bls), b1l = ld2(bls + 8);
                    MMA_BF16(acc2[s], ah0, ah1, ah2, ah3, b0h, b1h);
                    MMA_BF16(acc2[s], ah0, ah1, ah2, ah3, b0l, b1l);
                    MMA_BF16(acc2[s], al0, al1, al2, al3, b0h, b1h);
                }
            }
        }
        // epilogue2: relu -> out
        {
            int n0 = base + mi * 16 + gq;
            int n1 = n0 + 8;
#pragma unroll
            for (int s = 0; s < 4; s++) {
                int col0 = ni * 32 + s * 8 + tig * 2;
                if (n0 < N_NODES) {
                    float2 o;
                    o.x = fmaxf(acc2[s][0], 0.0f);
                    o.y = fmaxf(acc2[s][1], 0.0f);
                    *reinterpret_cast<float2*>(out + (size_t)n0 * NF + col0) = o;
                }
                if (n1 < N_NODES) {
                    float2 o;
                    o.x = fmaxf(acc2[s][2], 0.0f);
                    o.y = fmaxf(acc2[s][3], 0.0f);
                    *reinterpret_cast<float2*>(out + (size_t)n1 * NF + col0) = o;
                }
            }
        }

        if (tid == 0) s_tile = atomicAdd(&g_ctr, 1u);
        __syncthreads();
        tile = s_tile;
    }
}

// ---------------------------------------------------------------------------
extern "C" void kernel_launch(void* const* d_in, const int* in_sizes, int n_in,
                              void* d_out, int out_size)
{
    const float* edge_logits = (const float*)d_in[0];
    const float* edge_feats  = (const float*)d_in[1];
    const float* node_feats  = (const float*)d_in[2];
    const int*   dst         = (const int*)d_in[3];
    const float* W_et        = (const float*)d_in[4];
    const float* b_et        = (const float*)d_in[5];
    const float* W1          = (const float*)d_in[6];
    const float* b1          = (const float*)d_in[7];
    const float* W2          = (const float*)d_in[8];
    const float* b2          = (const float*)d_in[9];
    float* out = (float*)d_out;

    static int configured = 0;
    if (!configured) {
        cudaFuncSetAttribute(node_kernel,
                             cudaFuncAttributeMaxDynamicSharedMemorySize, SMEM_BYTES);
        configured = 1;
    }

    init_kernel<<<(NINIT + 255) / 256, 256>>>();
    edge_kernel<<<N_EDGES / 256, 256>>>(edge_logits, edge_feats, dst);
    node_kernel<<<152, 512, SMEM_BYTES>>>(node_feats, W_et, b_et,
                                          W1, b1, W2, b2, out);
}